// round 15
// baseline (speedup 1.0000x reference)
#include <cuda_runtime.h>
#include <cuda_bf16.h>
#include <stdint.h>

typedef unsigned int u32;
typedef unsigned long long u64;

#define NB 4
#define NT 4096
#define L2E 1.4426950408889634f

#define LDN 72    // natural [128][64] bf16 tiles: 144B rows (16B-mult, conflict-free)
#define LDT 136   // xT [64][128] bf16 tiles: 272B rows (16B-mult, conflict-free)

// ---- device-global scratch (allocation forbidden) ----
__device__ __align__(128) __nv_bfloat16 g_xHi[NB*NT*64];   // x natural [row][d]
__device__ __align__(128) __nv_bfloat16 g_xLo[NB*NT*64];
__device__ __align__(128) __nv_bfloat16 g_eHi[NB*NT*64];   // enc natural
__device__ __align__(128) __nv_bfloat16 g_eLo[NB*NT*64];
__device__ __align__(128) __nv_bfloat16 g_xTHi[NB*64*NT];  // xT [b][d][t]
__device__ __align__(128) __nv_bfloat16 g_xTLo[NB*64*NT];
__device__ float g_rz[NB*NT];                               // 1/Z_j

__device__ __forceinline__ float ex2f_(float x){
    float r; asm("ex2.approx.ftz.f32 %0, %1;" : "=f"(r) : "f"(x)); return r;
}
__device__ __forceinline__ void mma_bf16(float c[4], u32 a0,u32 a1,u32 a2,u32 a3,
                                         u32 b0,u32 b1){
    asm volatile("mma.sync.aligned.m16n8k16.row.col.f32.bf16.bf16.f32 "
        "{%0,%1,%2,%3}, {%4,%5,%6,%7}, {%8,%9}, {%0,%1,%2,%3};"
        : "+f"(c[0]),"+f"(c[1]),"+f"(c[2]),"+f"(c[3])
        : "r"(a0),"r"(a1),"r"(a2),"r"(a3),"r"(b0),"r"(b1));
}
// Non-trans ldmatrix: smem [n][k] row-major chunk -> B fragments directly.
__device__ __forceinline__ void ldm4(u32* r, u32 a){
    asm volatile("ldmatrix.sync.aligned.m8n8.x4.shared.b16 {%0,%1,%2,%3}, [%4];"
        : "=r"(r[0]),"=r"(r[1]),"=r"(r[2]),"=r"(r[3]) : "r"(a));
}
__device__ __forceinline__ u32 bits2(__nv_bfloat162 v){ return *(u32*)&v; }
__device__ __forceinline__ u32 smem_u32(const void* p){
    u32 a; asm("{ .reg .u64 t; cvta.to.shared.u64 t, %1; cvt.u32.u64 %0, t; }"
               : "=r"(a) : "l"(p)); return a;
}
__device__ __forceinline__ void cpa16(u32 dst, const void* src){
    asm volatile("cp.async.cg.shared.global [%0], [%1], 16;" :: "r"(dst), "l"(src));
}
#define CPA_COMMIT() asm volatile("cp.async.commit_group;" ::: "memory")
#define CPA_WAIT1()  asm volatile("cp.async.wait_group 1;" ::: "memory")
#define CPA_WAIT0()  asm volatile("cp.async.wait_group 0;" ::: "memory")

// stage a [128][64] bf16 natural tile into padded smem (LDN); NTHR threads
template<int NTHR>
__device__ __forceinline__ void stage_nat(u32 dh, u32 dl,
                                          const __nv_bfloat16* sh,
                                          const __nv_bfloat16* sl, int tid){
    #pragma unroll
    for (int idx = tid; idx < 1024; idx += NTHR) {
        int r = idx >> 3, c = idx & 7;
        u32 off = (u32)(r*LDN + c*8)*2;
        cpa16(dh + off, sh + r*64 + c*8);
        cpa16(dl + off, sl + r*64 + c*8);
    }
}
// stage a [64][128] bf16 xT tile (row stride 4096) into padded smem (LDT)
template<int NTHR>
__device__ __forceinline__ void stage_xt(u32 dh, u32 dl,
                                         const __nv_bfloat16* sh,
                                         const __nv_bfloat16* sl, int tid){
    #pragma unroll
    for (int idx = tid; idx < 1024; idx += NTHR) {
        int d = idx >> 4, c = idx & 15;
        u32 off = (u32)(d*LDT + c*8)*2;
        cpa16(dh + off, sh + (size_t)d*4096 + c*8);
        cpa16(dl + off, sl + (size_t)d*4096 + c*8);
    }
}

// ---------------------------------------------------------------------------
// Kernel 1: enc = tanh(softmax(x W1 + b1) W2 + b2).   (unchanged)
// ---------------------------------------------------------------------------
__global__ void __launch_bounds__(256) mlp_kernel(
    const float* __restrict__ x, const float* __restrict__ W1,
    const float* __restrict__ b1, const float* __restrict__ W2,
    const float* __restrict__ b2)
{
    __shared__ float sW1[64*64];
    __shared__ float sW2[64*64];
    __shared__ float sbuf[8][64];
    int tid = threadIdx.x;
    #pragma unroll
    for (int i = tid*4; i < 4096; i += 1024) {
        *(float4*)&sW1[i] = *(const float4*)&W1[i];
        *(float4*)&sW2[i] = *(const float4*)&W2[i];
    }
    int w = tid >> 5, lane = tid & 31;

    for (int q = 0; q < 4; q++) {
        int row = blockIdx.x*32 + q*8 + w;
        const float* xr = x + (size_t)row*64;
        float x0 = xr[lane], x1 = xr[lane+32];
        sbuf[w][lane] = x0; sbuf[w][lane+32] = x1;
        __syncthreads();
        {
            float v0 = sbuf[w][2*lane], v1 = sbuf[w][2*lane+1];
            __nv_bfloat162 h2 = __floats2bfloat162_rn(v0, v1);
            __nv_bfloat162 l2 = __floats2bfloat162_rn(v0 - __bfloat162float(h2.x),
                                                      v1 - __bfloat162float(h2.y));
            ((__nv_bfloat162*)g_xHi)[(size_t)row*32 + lane] = h2;
            ((__nv_bfloat162*)g_xLo)[(size_t)row*32 + lane] = l2;
        }
        if (tid < 64) {
            int rb = blockIdx.x*32 + q*8;
            int bb = rb >> 12, t0 = rb & 4095;
            __align__(16) __nv_bfloat16 hv[8], lv[8];
            #pragma unroll
            for (int qq = 0; qq < 8; qq++) {
                float v = sbuf[qq][tid];
                hv[qq] = __float2bfloat16(v);
                lv[qq] = __float2bfloat16(v - __bfloat162float(hv[qq]));
            }
            *(uint4*)&g_xTHi[((size_t)(bb*64+tid))*4096 + t0] = *(uint4*)hv;
            *(uint4*)&g_xTLo[((size_t)(bb*64+tid))*4096 + t0] = *(uint4*)lv;
        }
        float a0 = b1[lane], a1 = b1[lane+32];
        #pragma unroll
        for (int d = 0; d < 64; d++) {
            float xv = sbuf[w][d];
            a0 = fmaf(xv, sW1[d*64+lane   ], a0);
            a1 = fmaf(xv, sW1[d*64+lane+32], a1);
        }
        float mm = fmaxf(a0, a1);
        #pragma unroll
        for (int o = 16; o > 0; o >>= 1) mm = fmaxf(mm, __shfl_xor_sync(0xffffffffu, mm, o));
        float e0 = __expf(a0 - mm), e1 = __expf(a1 - mm);
        float ss = e0 + e1;
        #pragma unroll
        for (int o = 16; o > 0; o >>= 1) ss += __shfl_xor_sync(0xffffffffu, ss, o);
        float rs = 1.0f/ss;
        __syncthreads();
        sbuf[w][lane] = e0*rs; sbuf[w][lane+32] = e1*rs;
        __syncwarp();
        float c0 = b2[lane], c1 = b2[lane+32];
        #pragma unroll
        for (int d = 0; d < 64; d++) {
            float hv = sbuf[w][d];
            c0 = fmaf(hv, sW2[d*64+lane   ], c0);
            c1 = fmaf(hv, sW2[d*64+lane+32], c1);
        }
        float t0v = tanhf(c0), t1v = tanhf(c1);
        __syncwarp();
        sbuf[w][lane] = t0v; sbuf[w][lane+32] = t1v;
        __syncwarp();
        {
            float v0 = sbuf[w][2*lane], v1 = sbuf[w][2*lane+1];
            __nv_bfloat162 h2 = __floats2bfloat162_rn(v0, v1);
            __nv_bfloat162 l2 = __floats2bfloat162_rn(v0 - __bfloat162float(h2.x),
                                                      v1 - __bfloat162float(h2.y));
            ((__nv_bfloat162*)g_eHi)[(size_t)row*32 + lane] = h2;
            ((__nv_bfloat162*)g_eLo)[(size_t)row*32 + lane] = l2;
        }
        __syncwarp();
    }
}

// ---------------------------------------------------------------------------
// Kernel 2: Z_j = sum_i exp(x_j . enc_i); writes 1/Z.  512 threads:
// warp pair (w, w+8) shares j-band (w&7); w handles i-half 0, w+8 i-half 1.
// Partial Z combined via smem (reusing dead x-staging region).
// ---------------------------------------------------------------------------
__global__ void __launch_bounds__(512) stats_kernel()
{
    extern __shared__ char smc[];
    u32 smb = smem_u32(smc);
    const int O_X = 0, O_E = 36864, EBUF = 36864, NATB = 18432;
    int tid = threadIdx.x, w = tid>>5, lane = tid&31;
    int g = lane>>2, t = lane&3;
    int wm = w & 7, half = w >> 3;
    int b = blockIdx.x >> 5, j0 = (blockIdx.x & 31)*128;
    int row_l  = ((lane>>4)<<3) | (lane&7);
    int koff_l = ((lane>>3)&1)<<3;
    u32 lbaseN = (u32)(row_l*LDN + koff_l)*2;

    stage_nat<512>(smb+O_X, smb+O_X+NATB,
              g_xHi + (size_t)(b*4096+j0)*64,
              g_xLo + (size_t)(b*4096+j0)*64, tid);
    CPA_COMMIT();
    stage_nat<512>(smb+O_E, smb+O_E+NATB,
              g_eHi + (size_t)(b*4096)*64,
              g_eLo + (size_t)(b*4096)*64, tid);
    CPA_COMMIT();
    CPA_WAIT1();
    __syncthreads();

    const __nv_bfloat16* sXh = (const __nv_bfloat16*)(smc + O_X);
    const __nv_bfloat16* sXl = (const __nv_bfloat16*)(smc + O_X + NATB);
    u32 ah[4][4], al[4][4];
    int r0 = wm*16 + g;
    #pragma unroll
    for (int kt = 0; kt < 4; kt++) {
        int c0 = kt*16 + t*2;
        ah[kt][0] = *(u32*)&sXh[ r0   *LDN + c0];
        ah[kt][1] = *(u32*)&sXh[(r0+8)*LDN + c0];
        ah[kt][2] = *(u32*)&sXh[ r0   *LDN + c0+8];
        ah[kt][3] = *(u32*)&sXh[(r0+8)*LDN + c0+8];
        al[kt][0] = *(u32*)&sXl[ r0   *LDN + c0];
        al[kt][1] = *(u32*)&sXl[(r0+8)*LDN + c0];
        al[kt][2] = *(u32*)&sXl[ r0   *LDN + c0+8];
        al[kt][3] = *(u32*)&sXl[(r0+8)*LDN + c0+8];
    }
    float Z0 = 0.0f, Z1 = 0.0f;

    for (int it = 0; it < 32; ++it) {
        if (it+1 < 32) {
            stage_nat<512>(smb+O_E+((it+1)&1)*EBUF, smb+O_E+((it+1)&1)*EBUF+NATB,
                      g_eHi + (size_t)(b*4096+(it+1)*128)*64,
                      g_eLo + (size_t)(b*4096+(it+1)*128)*64, tid);
            CPA_COMMIT();
            CPA_WAIT1();
        } else {
            CPA_WAIT0();
        }
        __syncthreads();
        u32 eb = smb + O_E + (it&1)*EBUF + lbaseN;
        float c[8][4];
        #pragma unroll
        for (int n = 0; n < 8; n++)
            c[n][0]=c[n][1]=c[n][2]=c[n][3]=0.0f;
        #pragma unroll
        for (int kt = 0; kt < 4; kt++) {
            u32 BH[16], BL[16];
            #pragma unroll
            for (int nbp = 0; nbp < 4; nbp++) {
                u32 aH = eb + (u32)(((half*64 + nbp*16)*LDN + kt*16)*2);
                ldm4(BH + nbp*4, aH);
                ldm4(BL + nbp*4, aH + NATB);
            }
            #pragma unroll
            for (int n = 0; n < 8; n++) {
                u32 ix = (n>>1)*4 + (n&1)*2;
                mma_bf16(c[n], ah[kt][0],ah[kt][1],ah[kt][2],ah[kt][3], BH[ix],BH[ix+1]);
                mma_bf16(c[n], ah[kt][0],ah[kt][1],ah[kt][2],ah[kt][3], BL[ix],BL[ix+1]);
                mma_bf16(c[n], al[kt][0],al[kt][1],al[kt][2],al[kt][3], BH[ix],BH[ix+1]);
            }
        }
        #pragma unroll
        for (int n = 0; n < 8; n++) {
            Z0 += ex2f_(c[n][0]*L2E) + ex2f_(c[n][1]*L2E);
            Z1 += ex2f_(c[n][2]*L2E) + ex2f_(c[n][3]*L2E);
        }
        __syncthreads();
    }
    Z0 += __shfl_xor_sync(0xffffffffu, Z0, 1);
    Z0 += __shfl_xor_sync(0xffffffffu, Z0, 2);
    Z1 += __shfl_xor_sync(0xffffffffu, Z1, 1);
    Z1 += __shfl_xor_sync(0xffffffffu, Z1, 2);
    // combine warp-pair partials via smem (x-staging region is dead now)
    float* sZ = (float*)(smc + O_X);
    if (t == 0) {
        sZ[(w*8 + g)*2    ] = Z0;
        sZ[(w*8 + g)*2 + 1] = Z1;
    }
    __syncthreads();
    if (w < 8 && t == 0) {
        float z0 = sZ[(w*8+g)*2]     + sZ[((w+8)*8+g)*2];
        float z1 = sZ[(w*8+g)*2 + 1] + sZ[((w+8)*8+g)*2 + 1];
        g_rz[b*4096 + j0 + w*16 + g    ] = 1.0f/z0;
        g_rz[b*4096 + j0 + w*16 + g + 8] = 1.0f/z1;
    }
}

// ---------------------------------------------------------------------------
// Kernel 3: out[i,d] = sum_j ex2(s_ji*L2E)*rz_j * x[j,d].  512 threads:
// warp pair (w, w+8) shares i-band (w&7); w handles j-half 0, w+8 j-half 1.
// Partial acc combined via smem before the global store.
// ---------------------------------------------------------------------------
__global__ void __launch_bounds__(512) out_kernel(float* __restrict__ out)
{
    extern __shared__ char smc[];
    u32 smb = smem_u32(smc);
    const int O_E = 0, O_X = 36864, O_T = 110592, O_RZ = 180224;
    const int NATB = 18432, XBUF = 36864, TB = 17408, TBUF = 34816;
    int tid = threadIdx.x, w = tid>>5, lane = tid&31;
    int g = lane>>2, t = lane&3;
    int wm = w & 7, half = w >> 3;
    int b = blockIdx.x >> 5, i0 = (blockIdx.x & 31)*128;
    int row_l  = ((lane>>4)<<3) | (lane&7);
    int koff_l = ((lane>>3)&1)<<3;
    u32 lbaseN = (u32)(row_l*LDN + koff_l)*2;
    u32 lbaseT = (u32)(row_l*LDT + koff_l)*2;

    stage_nat<512>(smb+O_E, smb+O_E+NATB,
              g_eHi + (size_t)(b*4096+i0)*64,
              g_eLo + (size_t)(b*4096+i0)*64, tid);
    CPA_COMMIT();
    stage_nat<512>(smb+O_X, smb+O_X+NATB,
              g_xHi + (size_t)(b*4096)*64,
              g_xLo + (size_t)(b*4096)*64, tid);
    stage_xt<512>(smb+O_T, smb+O_T+TB,
             g_xTHi + ((size_t)b*64)*4096,
             g_xTLo + ((size_t)b*64)*4096, tid);
    if (tid < 32) cpa16(smb+O_RZ + tid*16, g_rz + b*4096 + tid*4);
    CPA_COMMIT();
    CPA_WAIT1();
    __syncthreads();

    const __nv_bfloat16* sEh = (const __nv_bfloat16*)(smc + O_E);
    const __nv_bfloat16* sEl = (const __nv_bfloat16*)(smc + O_E + NATB);
    u32 eh[4][4], el[4][4];
    int r0 = wm*16 + g;
    #pragma unroll
    for (int kt = 0; kt < 4; kt++) {
        int c0 = kt*16 + t*2;
        eh[kt][0] = *(u32*)&sEh[ r0   *LDN + c0];
        eh[kt][1] = *(u32*)&sEh[(r0+8)*LDN + c0];
        eh[kt][2] = *(u32*)&sEh[ r0   *LDN + c0+8];
        eh[kt][3] = *(u32*)&sEh[(r0+8)*LDN + c0+8];
        el[kt][0] = *(u32*)&sEl[ r0   *LDN + c0];
        el[kt][1] = *(u32*)&sEl[(r0+8)*LDN + c0];
        el[kt][2] = *(u32*)&sEl[ r0   *LDN + c0+8];
        el[kt][3] = *(u32*)&sEl[(r0+8)*LDN + c0+8];
    }
    float acc[8][4];
    #pragma unroll
    for (int n = 0; n < 8; n++)
        acc[n][0]=acc[n][1]=acc[n][2]=acc[n][3]=0.0f;

    for (int jt = 0; jt < 32; ++jt) {
        if (jt+1 < 32) {
            int nb = (jt+1) & 1;
            stage_nat<512>(smb+O_X+nb*XBUF, smb+O_X+nb*XBUF+NATB,
                      g_xHi + (size_t)(b*4096+(jt+1)*128)*64,
                      g_xLo + (size_t)(b*4096+(jt+1)*128)*64, tid);
            stage_xt<512>(smb+O_T+nb*TBUF, smb+O_T+nb*TBUF+TB,
                     g_xTHi + ((size_t)b*64)*4096 + (jt+1)*128,
                     g_xTLo + ((size_t)b*64)*4096 + (jt+1)*128, tid);
            if (tid < 32) cpa16(smb+O_RZ+nb*512 + tid*16,
                                g_rz + b*4096 + (jt+1)*128 + tid*4);
            CPA_COMMIT();
            CPA_WAIT1();
        } else {
            CPA_WAIT0();
        }
        __syncthreads();
        int cb = jt & 1;
        u32 xb = smb + O_X + cb*XBUF + lbaseN;
        u32 tb = smb + O_T + cb*TBUF + lbaseT;
        const float* sRZ = (const float*)(smc + O_RZ + cb*512);

        // MMA1: S^T[i][this warp's j-half]
        float c[8][4];
        #pragma unroll
        for (int n = 0; n < 8; n++)
            c[n][0]=c[n][1]=c[n][2]=c[n][3]=0.0f;
        #pragma unroll
        for (int kt = 0; kt < 4; kt++) {
            u32 BH[16], BL[16];
            #pragma unroll
            for (int nbp = 0; nbp < 4; nbp++) {
                u32 aH = xb + (u32)(((half*64 + nbp*16)*LDN + kt*16)*2);
                ldm4(BH + nbp*4, aH);
                ldm4(BL + nbp*4, aH + NATB);
            }
            #pragma unroll
            for (int n = 0; n < 8; n++) {
                u32 ix = (n>>1)*4 + (n&1)*2;
                mma_bf16(c[n], eh[kt][0],eh[kt][1],eh[kt][2],eh[kt][3], BH[ix],BH[ix+1]);
                mma_bf16(c[n], eh[kt][0],eh[kt][1],eh[kt][2],eh[kt][3], BL[ix],BL[ix+1]);
                mma_bf16(c[n], el[kt][0],el[kt][1],el[kt][2],el[kt][3], BH[ix],BH[ix+1]);
            }
        }
        // epilogue: p = ex2(s*L2E)*rz_j -> bf16 hi/lo A2 fragments (regs)
        u32 H0[8], H1[8], L0[8], L1[8];
        #pragma unroll
        for (int n = 0; n < 8; n++) {
            float rza = sRZ[half*64 + n*8 + t*2];
            float rzb = sRZ[half*64 + n*8 + t*2 + 1];
            float p0 = ex2f_(c[n][0]*L2E)*rza;
            float p1 = ex2f_(c[n][1]*L2E)*rzb;
            float p2 = ex2f_(c[n][2]*L2E)*rza;
            float p3 = ex2f_(c[n][3]*L2E)*rzb;
            __nv_bfloat162 h01 = __floats2bfloat162_rn(p0, p1);
            __nv_bfloat162 l01 = __floats2bfloat162_rn(p0 - __bfloat162float(h01.x),
                                                       p1 - __bfloat162float(h01.y));
            __nv_bfloat162 h23 = __floats2bfloat162_rn(p2, p3);
            __nv_bfloat162 l23 = __floats2bfloat162_rn(p2 - __bfloat162float(h23.x),
                                                       p3 - __bfloat162float(h23.y));
            H0[n] = bits2(h01); L0[n] = bits2(l01);
            H1[n] = bits2(h23); L1[n] = bits2(l23);
        }
        // MMA2: acc[i][d] += P^T(this half) * xT(this half)
        #pragma unroll
        for (int kt2 = 0; kt2 < 4; kt2++) {
            u32 a0 = H0[2*kt2], a2 = H0[2*kt2+1];
            u32 a1 = H1[2*kt2], a3 = H1[2*kt2+1];
            u32 q0 = L0[2*kt2], q2 = L0[2*kt2+1];
            u32 q1 = L1[2*kt2], q3 = L1[2*kt2+1];
            u32 TH[16], TL[16];
            #pragma unroll
            for (int nbp = 0; nbp < 4; nbp++) {
                u32 aT = tb + (u32)((nbp*16*LDT + half*64 + kt2*16)*2);
                ldm4(TH + nbp*4, aT);
                ldm4(TL + nbp*4, aT + TB);
            }
            #pragma unroll
            for (int n = 0; n < 8; n++) {
                u32 ix = (n>>1)*4 + (n&1)*2;
                mma_bf16(acc[n], a0,a1,a2,a3, TH[ix],TH[ix+1]);
                mma_bf16(acc[n], a0,a1,a2,a3, TL[ix],TL[ix+1]);
                mma_bf16(acc[n], q0,q1,q2,q3, TH[ix],TH[ix+1]);
            }
        }
        __syncthreads();
    }
    // combine warp-pair partials: warp w+8 dumps acc to smem, warp w adds.
    float* sred = (float*)(smc + O_X);     // 32KB, buffers now dead
    if (half == 1) {
        #pragma unroll
        for (int n = 0; n < 8; n++)
            *(float4*)&sred[(wm*32 + lane)*32 + n*4] =
                make_float4(acc[n][0], acc[n][1], acc[n][2], acc[n][3]);
    }
    __syncthreads();
    if (half == 0) {
        int i = i0 + 16*wm + g;
        #pragma unroll
        for (int n = 0; n < 8; n++) {
            float4 v = *(float4*)&sred[(wm*32 + lane)*32 + n*4];
            int d = n*8 + t*2;
            *(float2*)&out[((size_t)(b*4096 + i    ))*64 + d] =
                make_float2(acc[n][0] + v.x, acc[n][1] + v.y);
            *(float2*)&out[((size_t)(b*4096 + i + 8))*64 + d] =
                make_float2(acc[n][2] + v.z, acc[n][3] + v.w);
        }
    }
}

// ---------------------------------------------------------------------------
extern "C" void kernel_launch(void* const* d_in, const int* in_sizes, int n_in,
                              void* d_out, int out_size)
{
    (void)in_sizes; (void)n_in; (void)out_size;
    const float* x  = (const float*)d_in[0];
    const float* W1 = (const float*)d_in[1];
    const float* b1 = (const float*)d_in[2];
    const float* W2 = (const float*)d_in[3];
    const float* b2 = (const float*)d_in[4];
    float* out = (float*)d_out;

    const int SMEM_STATS = 110592;   // x(h+l) + 2 x enc(h+l) buffers
    const int SMEM_OUT   = 181248;   // enc + 2x x-buf + 2x xT-buf + 2x rz
    cudaFuncSetAttribute(stats_kernel, cudaFuncAttributeMaxDynamicSharedMemorySize, SMEM_STATS);
    cudaFuncSetAttribute(out_kernel,   cudaFuncAttributeMaxDynamicSharedMemorySize, SMEM_OUT);

    mlp_kernel<<<512, 256>>>(x, W1, b1, W2, b2);
    stats_kernel<<<128, 512, SMEM_STATS>>>();
    out_kernel<<<128, 512, SMEM_OUT>>>(out);
}

// round 16
// speedup vs baseline: 1.0590x; 1.0590x over previous
#include <cuda_runtime.h>
#include <cuda_bf16.h>
#include <stdint.h>

typedef unsigned int u32;
typedef unsigned long long u64;

#define NB 4
#define NT 4096
#define L2E 1.4426950408889634f

#define LDN 72    // natural [128][64] bf16 tiles: 144B rows — conflict-free for
                  // both non-trans (n-major) and trans (k-major) ldmatrix

// ---- device-global scratch (allocation forbidden) ----
__device__ __align__(128) __nv_bfloat16 g_xHi[NB*NT*64];   // x natural [row][d]
__device__ __align__(128) __nv_bfloat16 g_xLo[NB*NT*64];
__device__ __align__(128) __nv_bfloat16 g_eHi[NB*NT*64];   // enc natural
__device__ __align__(128) __nv_bfloat16 g_eLo[NB*NT*64];
__device__ float g_rz[NB*NT];                               // 1/Z_j

__device__ __forceinline__ float ex2f_(float x){
    float r; asm("ex2.approx.ftz.f32 %0, %1;" : "=f"(r) : "f"(x)); return r;
}
__device__ __forceinline__ void mma_bf16(float c[4], u32 a0,u32 a1,u32 a2,u32 a3,
                                         u32 b0,u32 b1){
    asm volatile("mma.sync.aligned.m16n8k16.row.col.f32.bf16.bf16.f32 "
        "{%0,%1,%2,%3}, {%4,%5,%6,%7}, {%8,%9}, {%0,%1,%2,%3};"
        : "+f"(c[0]),"+f"(c[1]),"+f"(c[2]),"+f"(c[3])
        : "r"(a0),"r"(a1),"r"(a2),"r"(a3),"r"(b0),"r"(b1));
}
// Non-trans ldmatrix: smem [n][k] row-major chunk -> B fragments directly.
__device__ __forceinline__ void ldm4(u32* r, u32 a){
    asm volatile("ldmatrix.sync.aligned.m8n8.x4.shared.b16 {%0,%1,%2,%3}, [%4];"
        : "=r"(r[0]),"=r"(r[1]),"=r"(r[2]),"=r"(r[3]) : "r"(a));
}
// Trans ldmatrix: smem [k][n] row-major chunk -> B fragments (k-major source).
__device__ __forceinline__ void ldm4t(u32* r, u32 a){
    asm volatile("ldmatrix.sync.aligned.m8n8.x4.trans.shared.b16 {%0,%1,%2,%3}, [%4];"
        : "=r"(r[0]),"=r"(r[1]),"=r"(r[2]),"=r"(r[3]) : "r"(a));
}
__device__ __forceinline__ u32 bits2(__nv_bfloat162 v){ return *(u32*)&v; }
__device__ __forceinline__ u32 smem_u32(const void* p){
    u32 a; asm("{ .reg .u64 t; cvta.to.shared.u64 t, %1; cvt.u32.u64 %0, t; }"
               : "=r"(a) : "l"(p)); return a;
}
__device__ __forceinline__ void cpa16(u32 dst, const void* src){
    asm volatile("cp.async.cg.shared.global [%0], [%1], 16;" :: "r"(dst), "l"(src));
}
#define CPA_COMMIT() asm volatile("cp.async.commit_group;" ::: "memory")
#define CPA_WAIT1()  asm volatile("cp.async.wait_group 1;" ::: "memory")
#define CPA_WAIT0()  asm volatile("cp.async.wait_group 0;" ::: "memory")

// stage a [128][64] bf16 natural tile into padded smem (LDN)
__device__ __forceinline__ void stage_nat(u32 dh, u32 dl,
                                          const __nv_bfloat16* sh,
                                          const __nv_bfloat16* sl, int tid){
    #pragma unroll
    for (int idx = tid; idx < 1024; idx += 256) {
        int r = idx >> 3, c = idx & 7;
        u32 off = (u32)(r*LDN + c*8)*2;
        cpa16(dh + off, sh + r*64 + c*8);
        cpa16(dl + off, sl + r*64 + c*8);
    }
}

// ---------------------------------------------------------------------------
// Kernel 1: enc = tanh(softmax(x W1 + b1) W2 + b2).
// Warp-autonomous after the W smem fill (one block sync); 4-way FMA partials.
// ---------------------------------------------------------------------------
__global__ void __launch_bounds__(256) mlp_kernel(
    const float* __restrict__ x, const float* __restrict__ W1,
    const float* __restrict__ b1, const float* __restrict__ W2,
    const float* __restrict__ b2)
{
    __shared__ float sW1[64*64];
    __shared__ float sW2[64*64];
    __shared__ float sbuf[8][64];
    int tid = threadIdx.x;
    #pragma unroll
    for (int i = tid*4; i < 4096; i += 1024) {
        *(float4*)&sW1[i] = *(const float4*)&W1[i];
        *(float4*)&sW2[i] = *(const float4*)&W2[i];
    }
    int w = tid >> 5, lane = tid & 31;
    __syncthreads();                          // W1/W2 ready (only block sync)

    for (int q = 0; q < 4; q++) {
        int row = blockIdx.x*32 + q*8 + w;
        const float* xr = x + (size_t)row*64;
        float x0 = xr[lane], x1 = xr[lane+32];
        sbuf[w][lane] = x0; sbuf[w][lane+32] = x1;
        __syncwarp();
        {
            float v0 = sbuf[w][2*lane], v1 = sbuf[w][2*lane+1];
            __nv_bfloat162 h2 = __floats2bfloat162_rn(v0, v1);
            __nv_bfloat162 l2 = __floats2bfloat162_rn(v0 - __bfloat162float(h2.x),
                                                      v1 - __bfloat162float(h2.y));
            ((__nv_bfloat162*)g_xHi)[(size_t)row*32 + lane] = h2;
            ((__nv_bfloat162*)g_xLo)[(size_t)row*32 + lane] = l2;
        }
        float s00=0,s01=0,s02=0,s03=0, s10=0,s11=0,s12=0,s13=0;
        #pragma unroll
        for (int d = 0; d < 64; d += 4) {
            float v0 = sbuf[w][d], v1 = sbuf[w][d+1];
            float v2 = sbuf[w][d+2], v3 = sbuf[w][d+3];
            s00 = fmaf(v0, sW1[(d  )*64+lane], s00);
            s01 = fmaf(v1, sW1[(d+1)*64+lane], s01);
            s02 = fmaf(v2, sW1[(d+2)*64+lane], s02);
            s03 = fmaf(v3, sW1[(d+3)*64+lane], s03);
            s10 = fmaf(v0, sW1[(d  )*64+lane+32], s10);
            s11 = fmaf(v1, sW1[(d+1)*64+lane+32], s11);
            s12 = fmaf(v2, sW1[(d+2)*64+lane+32], s12);
            s13 = fmaf(v3, sW1[(d+3)*64+lane+32], s13);
        }
        float a0 = b1[lane]    + ((s00+s01)+(s02+s03));
        float a1 = b1[lane+32] + ((s10+s11)+(s12+s13));
        float mm = fmaxf(a0, a1);
        #pragma unroll
        for (int o = 16; o > 0; o >>= 1) mm = fmaxf(mm, __shfl_xor_sync(0xffffffffu, mm, o));
        float e0 = __expf(a0 - mm), e1 = __expf(a1 - mm);
        float ss = e0 + e1;
        #pragma unroll
        for (int o = 16; o > 0; o >>= 1) ss += __shfl_xor_sync(0xffffffffu, ss, o);
        float rs = 1.0f/ss;
        __syncwarp();
        sbuf[w][lane] = e0*rs; sbuf[w][lane+32] = e1*rs;
        __syncwarp();
        s00=0;s01=0;s02=0;s03=0; s10=0;s11=0;s12=0;s13=0;
        #pragma unroll
        for (int d = 0; d < 64; d += 4) {
            float v0 = sbuf[w][d], v1 = sbuf[w][d+1];
            float v2 = sbuf[w][d+2], v3 = sbuf[w][d+3];
            s00 = fmaf(v0, sW2[(d  )*64+lane], s00);
            s01 = fmaf(v1, sW2[(d+1)*64+lane], s01);
            s02 = fmaf(v2, sW2[(d+2)*64+lane], s02);
            s03 = fmaf(v3, sW2[(d+3)*64+lane], s03);
            s10 = fmaf(v0, sW2[(d  )*64+lane+32], s10);
            s11 = fmaf(v1, sW2[(d+1)*64+lane+32], s11);
            s12 = fmaf(v2, sW2[(d+2)*64+lane+32], s12);
            s13 = fmaf(v3, sW2[(d+3)*64+lane+32], s13);
        }
        float c0 = b2[lane]    + ((s00+s01)+(s02+s03));
        float c1 = b2[lane+32] + ((s10+s11)+(s12+s13));
        float t0v = tanhf(c0), t1v = tanhf(c1);
        __syncwarp();
        sbuf[w][lane] = t0v; sbuf[w][lane+32] = t1v;
        __syncwarp();
        {
            float v0 = sbuf[w][2*lane], v1 = sbuf[w][2*lane+1];
            __nv_bfloat162 h2 = __floats2bfloat162_rn(v0, v1);
            __nv_bfloat162 l2 = __floats2bfloat162_rn(v0 - __bfloat162float(h2.x),
                                                      v1 - __bfloat162float(h2.y));
            ((__nv_bfloat162*)g_eHi)[(size_t)row*32 + lane] = h2;
            ((__nv_bfloat162*)g_eLo)[(size_t)row*32 + lane] = l2;
        }
        __syncwarp();
    }
}

// ---------------------------------------------------------------------------
// Kernel 2: Z_j = sum_i exp(x_j . enc_i); writes 1/Z.  (R14 structure)
// ---------------------------------------------------------------------------
__global__ void __launch_bounds__(256) stats_kernel()
{
    extern __shared__ char smc[];
    u32 smb = smem_u32(smc);
    const int O_X = 0, O_E = 36864, EBUF = 36864, NATB = 18432;
    int tid = threadIdx.x, w = tid>>5, lane = tid&31;
    int g = lane>>2, t = lane&3;
    int b = blockIdx.x >> 5, j0 = (blockIdx.x & 31)*128;
    int row_l  = ((lane>>4)<<3) | (lane&7);
    int koff_l = ((lane>>3)&1)<<3;
    u32 lbaseN = (u32)(row_l*LDN + koff_l)*2;

    stage_nat(smb+O_X, smb+O_X+NATB,
              g_xHi + (size_t)(b*4096+j0)*64,
              g_xLo + (size_t)(b*4096+j0)*64, tid);
    CPA_COMMIT();
    stage_nat(smb+O_E, smb+O_E+NATB,
              g_eHi + (size_t)(b*4096)*64,
              g_eLo + (size_t)(b*4096)*64, tid);
    CPA_COMMIT();
    CPA_WAIT1();
    __syncthreads();

    const __nv_bfloat16* sXh = (const __nv_bfloat16*)(smc + O_X);
    const __nv_bfloat16* sXl = (const __nv_bfloat16*)(smc + O_X + NATB);
    u32 ah[4][4], al[4][4];
    int r0 = w*16 + g;
    #pragma unroll
    for (int kt = 0; kt < 4; kt++) {
        int c0 = kt*16 + t*2;
        ah[kt][0] = *(u32*)&sXh[ r0   *LDN + c0];
        ah[kt][1] = *(u32*)&sXh[(r0+8)*LDN + c0];
        ah[kt][2] = *(u32*)&sXh[ r0   *LDN + c0+8];
        ah[kt][3] = *(u32*)&sXh[(r0+8)*LDN + c0+8];
        al[kt][0] = *(u32*)&sXl[ r0   *LDN + c0];
        al[kt][1] = *(u32*)&sXl[(r0+8)*LDN + c0];
        al[kt][2] = *(u32*)&sXl[ r0   *LDN + c0+8];
        al[kt][3] = *(u32*)&sXl[(r0+8)*LDN + c0+8];
    }
    float Z0 = 0.0f, Z1 = 0.0f;

    for (int it = 0; it < 32; ++it) {
        if (it+1 < 32) {
            stage_nat(smb+O_E+((it+1)&1)*EBUF, smb+O_E+((it+1)&1)*EBUF+NATB,
                      g_eHi + (size_t)(b*4096+(it+1)*128)*64,
                      g_eLo + (size_t)(b*4096+(it+1)*128)*64, tid);
            CPA_COMMIT();
            CPA_WAIT1();
        } else {
            CPA_WAIT0();
        }
        __syncthreads();
        u32 eb = smb + O_E + (it&1)*EBUF + lbaseN;
        #pragma unroll
        for (int half = 0; half < 2; half++) {
            float c[8][4];
            #pragma unroll
            for (int n = 0; n < 8; n++)
                c[n][0]=c[n][1]=c[n][2]=c[n][3]=0.0f;
            #pragma unroll
            for (int kt = 0; kt < 4; kt++) {
                u32 BH[16], BL[16];
                #pragma unroll
                for (int nbp = 0; nbp < 4; nbp++) {
                    u32 aH = eb + (u32)(((half*64 + nbp*16)*LDN + kt*16)*2);
                    ldm4(BH + nbp*4, aH);
                    ldm4(BL + nbp*4, aH + NATB);
                }
                #pragma unroll
                for (int n = 0; n < 8; n++) {
                    u32 ix = (n>>1)*4 + (n&1)*2;
                    mma_bf16(c[n], ah[kt][0],ah[kt][1],ah[kt][2],ah[kt][3], BH[ix],BH[ix+1]);
                    mma_bf16(c[n], ah[kt][0],ah[kt][1],ah[kt][2],ah[kt][3], BL[ix],BL[ix+1]);
                    mma_bf16(c[n], al[kt][0],al[kt][1],al[kt][2],al[kt][3], BH[ix],BH[ix+1]);
                }
            }
            #pragma unroll
            for (int n = 0; n < 8; n++) {
                Z0 += ex2f_(c[n][0]*L2E) + ex2f_(c[n][1]*L2E);
                Z1 += ex2f_(c[n][2]*L2E) + ex2f_(c[n][3]*L2E);
            }
        }
        __syncthreads();
    }
    Z0 += __shfl_xor_sync(0xffffffffu, Z0, 1);
    Z0 += __shfl_xor_sync(0xffffffffu, Z0, 2);
    Z1 += __shfl_xor_sync(0xffffffffu, Z1, 1);
    Z1 += __shfl_xor_sync(0xffffffffu, Z1, 2);
    if (t == 0) {
        g_rz[b*4096 + j0 + w*16 + g    ] = 1.0f/Z0;
        g_rz[b*4096 + j0 + w*16 + g + 8] = 1.0f/Z1;
    }
}

// ---------------------------------------------------------------------------
// Kernel 3: out[i,d] = sum_j ex2(s_ji*L2E)*rz_j * x[j,d].
// MMA2 B now comes from the SAME natural x tile via ldmatrix.trans — the xT
// copy (global arrays, staging, smem buffers) is gone.
// ---------------------------------------------------------------------------
__global__ void __launch_bounds__(256) out_kernel(float* __restrict__ out)
{
    extern __shared__ char smc[];
    u32 smb = smem_u32(smc);
    const int O_E = 0, O_X = 36864, O_RZ = 110592;
    const int NATB = 18432, XBUF = 36864;
    int tid = threadIdx.x, w = tid>>5, lane = tid&31;
    int g = lane>>2, t = lane&3;
    int b = blockIdx.x >> 5, i0 = (blockIdx.x & 31)*128;
    // non-trans (MMA1 B: rows = n = j)
    int row_l  = ((lane>>4)<<3) | (lane&7);
    int koff_l = ((lane>>3)&1)<<3;
    u32 lbaseN = (u32)(row_l*LDN + koff_l)*2;
    // trans (MMA2 B: rows = k = j, cols = n = d)
    int rowT = (((lane>>3)&1)<<3) | (lane&7);
    int colT = (lane>>4)<<3;
    u32 lbaseT = (u32)(rowT*LDN + colT)*2;

    stage_nat(smb+O_E, smb+O_E+NATB,
              g_eHi + (size_t)(b*4096+i0)*64,
              g_eLo + (size_t)(b*4096+i0)*64, tid);
    CPA_COMMIT();
    stage_nat(smb+O_X, smb+O_X+NATB,
              g_xHi + (size_t)(b*4096)*64,
              g_xLo + (size_t)(b*4096)*64, tid);
    if (tid < 32) cpa16(smb+O_RZ + tid*16, g_rz + b*4096 + tid*4);
    CPA_COMMIT();
    CPA_WAIT1();
    __syncthreads();

    const __nv_bfloat16* sEh = (const __nv_bfloat16*)(smc + O_E);
    const __nv_bfloat16* sEl = (const __nv_bfloat16*)(smc + O_E + NATB);
    u32 eh[4][4], el[4][4];
    int r0 = w*16 + g;
    #pragma unroll
    for (int kt = 0; kt < 4; kt++) {
        int c0 = kt*16 + t*2;
        eh[kt][0] = *(u32*)&sEh[ r0   *LDN + c0];
        eh[kt][1] = *(u32*)&sEh[(r0+8)*LDN + c0];
        eh[kt][2] = *(u32*)&sEh[ r0   *LDN + c0+8];
        eh[kt][3] = *(u32*)&sEh[(r0+8)*LDN + c0+8];
        el[kt][0] = *(u32*)&sEl[ r0   *LDN + c0];
        el[kt][1] = *(u32*)&sEl[(r0+8)*LDN + c0];
        el[kt][2] = *(u32*)&sEl[ r0   *LDN + c0+8];
        el[kt][3] = *(u32*)&sEl[(r0+8)*LDN + c0+8];
    }
    float acc[8][4];
    #pragma unroll
    for (int n = 0; n < 8; n++)
        acc[n][0]=acc[n][1]=acc[n][2]=acc[n][3]=0.0f;

    for (int jt = 0; jt < 32; ++jt) {
        if (jt+1 < 32) {
            int nb = (jt+1) & 1;
            stage_nat(smb+O_X+nb*XBUF, smb+O_X+nb*XBUF+NATB,
                      g_xHi + (size_t)(b*4096+(jt+1)*128)*64,
                      g_xLo + (size_t)(b*4096+(jt+1)*128)*64, tid);
            if (tid < 32) cpa16(smb+O_RZ+nb*512 + tid*16,
                                g_rz + b*4096 + (jt+1)*128 + tid*4);
            CPA_COMMIT();
            CPA_WAIT1();
        } else {
            CPA_WAIT0();
        }
        __syncthreads();
        int cb = jt & 1;
        u32 xbN = smb + O_X + cb*XBUF + lbaseN;
        u32 xbT = smb + O_X + cb*XBUF + lbaseT;
        const float* sRZ = (const float*)(smc + O_RZ + cb*512);

        #pragma unroll
        for (int half = 0; half < 2; half++) {
            // MMA1: S^T[i][j-half 64]
            float c[8][4];
            #pragma unroll
            for (int n = 0; n < 8; n++)
                c[n][0]=c[n][1]=c[n][2]=c[n][3]=0.0f;
            #pragma unroll
            for (int kt = 0; kt < 4; kt++) {
                u32 BH[16], BL[16];
                #pragma unroll
                for (int nbp = 0; nbp < 4; nbp++) {
                    u32 aH = xbN + (u32)(((half*64 + nbp*16)*LDN + kt*16)*2);
                    ldm4(BH + nbp*4, aH);
                    ldm4(BL + nbp*4, aH + NATB);
                }
                #pragma unroll
                for (int n = 0; n < 8; n++) {
                    u32 ix = (n>>1)*4 + (n&1)*2;
                    mma_bf16(c[n], eh[kt][0],eh[kt][1],eh[kt][2],eh[kt][3], BH[ix],BH[ix+1]);
                    mma_bf16(c[n], eh[kt][0],eh[kt][1],eh[kt][2],eh[kt][3], BL[ix],BL[ix+1]);
                    mma_bf16(c[n], el[kt][0],el[kt][1],el[kt][2],el[kt][3], BH[ix],BH[ix+1]);
                }
            }
            // epilogue: p = ex2(s*L2E)*rz_j -> bf16 hi/lo A2 fragments (regs)
            u32 H0[8], H1[8], L0[8], L1[8];
            #pragma unroll
            for (int n = 0; n < 8; n++) {
                float rza = sRZ[half*64 + n*8 + t*2];
                float rzb = sRZ[half*64 + n*8 + t*2 + 1];
                float p0 = ex2f_(c[n][0]*L2E)*rza;
                float p1 = ex2f_(c[n][1]*L2E)*rzb;
                float p2 = ex2f_(c[n][2]*L2E)*rza;
                float p3 = ex2f_(c[n][3]*L2E)*rzb;
                __nv_bfloat162 h01 = __floats2bfloat162_rn(p0, p1);
                __nv_bfloat162 l01 = __floats2bfloat162_rn(p0 - __bfloat162float(h01.x),
                                                           p1 - __bfloat162float(h01.y));
                __nv_bfloat162 h23 = __floats2bfloat162_rn(p2, p3);
                __nv_bfloat162 l23 = __floats2bfloat162_rn(p2 - __bfloat162float(h23.x),
                                                           p3 - __bfloat162float(h23.y));
                H0[n] = bits2(h01); L0[n] = bits2(l01);
                H1[n] = bits2(h23); L1[n] = bits2(l23);
            }
            // MMA2: acc[i][d] += P^T(half) * x(half) via trans-ldmatrix
            #pragma unroll
            for (int kt2 = 0; kt2 < 4; kt2++) {
                u32 a0 = H0[2*kt2], a2 = H0[2*kt2+1];
                u32 a1 = H1[2*kt2], a3 = H1[2*kt2+1];
                u32 q0 = L0[2*kt2], q2 = L0[2*kt2+1];
                u32 q1 = L1[2*kt2], q3 = L1[2*kt2+1];
                u32 TH[16], TL[16];
                #pragma unroll
                for (int nbp = 0; nbp < 4; nbp++) {
                    u32 aT = xbT + (u32)(((half*64 + kt2*16)*LDN + nbp*16)*2);
                    ldm4t(TH + nbp*4, aT);
                    ldm4t(TL + nbp*4, aT + NATB);
                }
                #pragma unroll
                for (int n = 0; n < 8; n++) {
                    u32 ix = (n>>1)*4 + (n&1)*2;
                    mma_bf16(acc[n], a0,a1,a2,a3, TH[ix],TH[ix+1]);
                    mma_bf16(acc[n], a0,a1,a2,a3, TL[ix],TL[ix+1]);
                    mma_bf16(acc[n], q0,q1,q2,q3, TH[ix],TH[ix+1]);
                }
            }
        }
        __syncthreads();
    }
    // store: acc[n][0..1] -> (i=16w+g, d=n*8+t*2), acc[n][2..3] -> row +8
    int i = i0 + 16*w + g;
    #pragma unroll
    for (int n = 0; n < 8; n++) {
        int d = n*8 + t*2;
        *(float2*)&out[((size_t)(b*4096 + i    ))*64 + d] = make_float2(acc[n][0], acc[n][1]);
        *(float2*)&out[((size_t)(b*4096 + i + 8))*64 + d] = make_float2(acc[n][2], acc[n][3]);
    }
}

// ---------------------------------------------------------------------------
extern "C" void kernel_launch(void* const* d_in, const int* in_sizes, int n_in,
                              void* d_out, int out_size)
{
    (void)in_sizes; (void)n_in; (void)out_size;
    const float* x  = (const float*)d_in[0];
    const float* W1 = (const float*)d_in[1];
    const float* b1 = (const float*)d_in[2];
    const float* W2 = (const float*)d_in[3];
    const float* b2 = (const float*)d_in[4];
    float* out = (float*)d_out;

    const int SMEM_STATS = 110592;   // x(h+l) + 2 x enc(h+l) buffers
    const int SMEM_OUT   = 111616;   // enc(h+l) + 2x x-buf(h+l) + 2x rz
    cudaFuncSetAttribute(stats_kernel, cudaFuncAttributeMaxDynamicSharedMemorySize, SMEM_STATS);
    cudaFuncSetAttribute(out_kernel,   cudaFuncAttributeMaxDynamicSharedMemorySize, SMEM_OUT);

    mlp_kernel<<<512, 256>>>(x, W1, b1, W2, b2);
    stats_kernel<<<128, 256, SMEM_STATS>>>();
    out_kernel<<<128, 256, SMEM_OUT>>>(out);
}

// round 17
// speedup vs baseline: 1.0603x; 1.0012x over previous
#include <cuda_runtime.h>
#include <cuda_bf16.h>
#include <stdint.h>

typedef unsigned int u32;
typedef unsigned long long u64;

#define NB 4
#define NT 4096
#define L2E 1.4426950408889634f

#define LDN 72    // natural [128][64] bf16 tiles: 144B rows — conflict-free for
                  // both non-trans (n-major) and trans (k-major) ldmatrix

// ---- device-global scratch (allocation forbidden) ----
__device__ __align__(128) __nv_bfloat16 g_xHi[NB*NT*64];   // x natural [row][d]
__device__ __align__(128) __nv_bfloat16 g_xLo[NB*NT*64];
__device__ __align__(128) __nv_bfloat16 g_eHi[NB*NT*64];   // enc natural
__device__ __align__(128) __nv_bfloat16 g_eLo[NB*NT*64];
__device__ float g_rz[NB*NT];                               // 1/Z_j

__device__ __forceinline__ float ex2f_(float x){
    float r; asm("ex2.approx.ftz.f32 %0, %1;" : "=f"(r) : "f"(x)); return r;
}
__device__ __forceinline__ void mma_bf16(float c[4], u32 a0,u32 a1,u32 a2,u32 a3,
                                         u32 b0,u32 b1){
    asm volatile("mma.sync.aligned.m16n8k16.row.col.f32.bf16.bf16.f32 "
        "{%0,%1,%2,%3}, {%4,%5,%6,%7}, {%8,%9}, {%0,%1,%2,%3};"
        : "+f"(c[0]),"+f"(c[1]),"+f"(c[2]),"+f"(c[3])
        : "r"(a0),"r"(a1),"r"(a2),"r"(a3),"r"(b0),"r"(b1));
}
// Non-trans ldmatrix: smem [n][k] row-major chunk -> B fragments directly.
__device__ __forceinline__ void ldm4(u32* r, u32 a){
    asm volatile("ldmatrix.sync.aligned.m8n8.x4.shared.b16 {%0,%1,%2,%3}, [%4];"
        : "=r"(r[0]),"=r"(r[1]),"=r"(r[2]),"=r"(r[3]) : "r"(a));
}
// Trans ldmatrix: smem [k][n] row-major chunk -> B fragments (k-major source).
__device__ __forceinline__ void ldm4t(u32* r, u32 a){
    asm volatile("ldmatrix.sync.aligned.m8n8.x4.trans.shared.b16 {%0,%1,%2,%3}, [%4];"
        : "=r"(r[0]),"=r"(r[1]),"=r"(r[2]),"=r"(r[3]) : "r"(a));
}
__device__ __forceinline__ u32 bits2(__nv_bfloat162 v){ return *(u32*)&v; }
__device__ __forceinline__ u32 smem_u32(const void* p){
    u32 a; asm("{ .reg .u64 t; cvta.to.shared.u64 t, %1; cvt.u32.u64 %0, t; }"
               : "=r"(a) : "l"(p)); return a;
}
__device__ __forceinline__ void cpa16(u32 dst, const void* src){
    asm volatile("cp.async.cg.shared.global [%0], [%1], 16;" :: "r"(dst), "l"(src));
}
#define CPA_COMMIT() asm volatile("cp.async.commit_group;" ::: "memory")
#define CPA_WAIT1()  asm volatile("cp.async.wait_group 1;" ::: "memory")
#define CPA_WAIT0()  asm volatile("cp.async.wait_group 0;" ::: "memory")

// stage a [128][64] bf16 natural tile into padded smem (LDN)
__device__ __forceinline__ void stage_nat(u32 dh, u32 dl,
                                          const __nv_bfloat16* sh,
                                          const __nv_bfloat16* sl, int tid){
    #pragma unroll
    for (int idx = tid; idx < 1024; idx += 256) {
        int r = idx >> 3, c = idx & 7;
        u32 off = (u32)(r*LDN + c*8)*2;
        cpa16(dh + off, sh + r*64 + c*8);
        cpa16(dl + off, sl + r*64 + c*8);
    }
}

// ---------------------------------------------------------------------------
// Kernel 1: enc = tanh(softmax(x W1 + b1) W2 + b2).
// Warp-autonomous after the W smem fill (one block sync); 4-way FMA partials.
// ---------------------------------------------------------------------------
__global__ void __launch_bounds__(256) mlp_kernel(
    const float* __restrict__ x, const float* __restrict__ W1,
    const float* __restrict__ b1, const float* __restrict__ W2,
    const float* __restrict__ b2)
{
    __shared__ float sW1[64*64];
    __shared__ float sW2[64*64];
    __shared__ float sbuf[8][64];
    int tid = threadIdx.x;
    #pragma unroll
    for (int i = tid*4; i < 4096; i += 1024) {
        *(float4*)&sW1[i] = *(const float4*)&W1[i];
        *(float4*)&sW2[i] = *(const float4*)&W2[i];
    }
    int w = tid >> 5, lane = tid & 31;
    __syncthreads();                          // W1/W2 ready (only block sync)

    for (int q = 0; q < 4; q++) {
        int row = blockIdx.x*32 + q*8 + w;
        const float* xr = x + (size_t)row*64;
        float x0 = xr[lane], x1 = xr[lane+32];
        sbuf[w][lane] = x0; sbuf[w][lane+32] = x1;
        __syncwarp();
        {
            float v0 = sbuf[w][2*lane], v1 = sbuf[w][2*lane+1];
            __nv_bfloat162 h2 = __floats2bfloat162_rn(v0, v1);
            __nv_bfloat162 l2 = __floats2bfloat162_rn(v0 - __bfloat162float(h2.x),
                                                      v1 - __bfloat162float(h2.y));
            ((__nv_bfloat162*)g_xHi)[(size_t)row*32 + lane] = h2;
            ((__nv_bfloat162*)g_xLo)[(size_t)row*32 + lane] = l2;
        }
        float s00=0,s01=0,s02=0,s03=0, s10=0,s11=0,s12=0,s13=0;
        #pragma unroll
        for (int d = 0; d < 64; d += 4) {
            float v0 = sbuf[w][d], v1 = sbuf[w][d+1];
            float v2 = sbuf[w][d+2], v3 = sbuf[w][d+3];
            s00 = fmaf(v0, sW1[(d  )*64+lane], s00);
            s01 = fmaf(v1, sW1[(d+1)*64+lane], s01);
            s02 = fmaf(v2, sW1[(d+2)*64+lane], s02);
            s03 = fmaf(v3, sW1[(d+3)*64+lane], s03);
            s10 = fmaf(v0, sW1[(d  )*64+lane+32], s10);
            s11 = fmaf(v1, sW1[(d+1)*64+lane+32], s11);
            s12 = fmaf(v2, sW1[(d+2)*64+lane+32], s12);
            s13 = fmaf(v3, sW1[(d+3)*64+lane+32], s13);
        }
        float a0 = b1[lane]    + ((s00+s01)+(s02+s03));
        float a1 = b1[lane+32] + ((s10+s11)+(s12+s13));
        float mm = fmaxf(a0, a1);
        #pragma unroll
        for (int o = 16; o > 0; o >>= 1) mm = fmaxf(mm, __shfl_xor_sync(0xffffffffu, mm, o));
        float e0 = __expf(a0 - mm), e1 = __expf(a1 - mm);
        float ss = e0 + e1;
        #pragma unroll
        for (int o = 16; o > 0; o >>= 1) ss += __shfl_xor_sync(0xffffffffu, ss, o);
        float rs = 1.0f/ss;
        __syncwarp();
        sbuf[w][lane] = e0*rs; sbuf[w][lane+32] = e1*rs;
        __syncwarp();
        s00=0;s01=0;s02=0;s03=0; s10=0;s11=0;s12=0;s13=0;
        #pragma unroll
        for (int d = 0; d < 64; d += 4) {
            float v0 = sbuf[w][d], v1 = sbuf[w][d+1];
            float v2 = sbuf[w][d+2], v3 = sbuf[w][d+3];
            s00 = fmaf(v0, sW2[(d  )*64+lane], s00);
            s01 = fmaf(v1, sW2[(d+1)*64+lane], s01);
            s02 = fmaf(v2, sW2[(d+2)*64+lane], s02);
            s03 = fmaf(v3, sW2[(d+3)*64+lane], s03);
            s10 = fmaf(v0, sW2[(d  )*64+lane+32], s10);
            s11 = fmaf(v1, sW2[(d+1)*64+lane+32], s11);
            s12 = fmaf(v2, sW2[(d+2)*64+lane+32], s12);
            s13 = fmaf(v3, sW2[(d+3)*64+lane+32], s13);
        }
        float c0 = b2[lane]    + ((s00+s01)+(s02+s03));
        float c1 = b2[lane+32] + ((s10+s11)+(s12+s13));
        float t0v = tanhf(c0), t1v = tanhf(c1);
        __syncwarp();
        sbuf[w][lane] = t0v; sbuf[w][lane+32] = t1v;
        __syncwarp();
        {
            float v0 = sbuf[w][2*lane], v1 = sbuf[w][2*lane+1];
            __nv_bfloat162 h2 = __floats2bfloat162_rn(v0, v1);
            __nv_bfloat162 l2 = __floats2bfloat162_rn(v0 - __bfloat162float(h2.x),
                                                      v1 - __bfloat162float(h2.y));
            ((__nv_bfloat162*)g_eHi)[(size_t)row*32 + lane] = h2;
            ((__nv_bfloat162*)g_eLo)[(size_t)row*32 + lane] = l2;
        }
        __syncwarp();
    }
}

// ---------------------------------------------------------------------------
// Kernel 2: Z_j = sum_i exp(x_j . enc_i); writes 1/Z.  (R14 structure)
// ---------------------------------------------------------------------------
__global__ void __launch_bounds__(256) stats_kernel()
{
    extern __shared__ char smc[];
    u32 smb = smem_u32(smc);
    const int O_X = 0, O_E = 36864, EBUF = 36864, NATB = 18432;
    int tid = threadIdx.x, w = tid>>5, lane = tid&31;
    int g = lane>>2, t = lane&3;
    int b = blockIdx.x >> 5, j0 = (blockIdx.x & 31)*128;
    int row_l  = ((lane>>4)<<3) | (lane&7);
    int koff_l = ((lane>>3)&1)<<3;
    u32 lbaseN = (u32)(row_l*LDN + koff_l)*2;

    stage_nat(smb+O_X, smb+O_X+NATB,
              g_xHi + (size_t)(b*4096+j0)*64,
              g_xLo + (size_t)(b*4096+j0)*64, tid);
    CPA_COMMIT();
    stage_nat(smb+O_E, smb+O_E+NATB,
              g_eHi + (size_t)(b*4096)*64,
              g_eLo + (size_t)(b*4096)*64, tid);
    CPA_COMMIT();
    CPA_WAIT1();
    __syncthreads();

    const __nv_bfloat16* sXh = (const __nv_bfloat16*)(smc + O_X);
    const __nv_bfloat16* sXl = (const __nv_bfloat16*)(smc + O_X + NATB);
    u32 ah[4][4], al[4][4];
    int r0 = w*16 + g;
    #pragma unroll
    for (int kt = 0; kt < 4; kt++) {
        int c0 = kt*16 + t*2;
        ah[kt][0] = *(u32*)&sXh[ r0   *LDN + c0];
        ah[kt][1] = *(u32*)&sXh[(r0+8)*LDN + c0];
        ah[kt][2] = *(u32*)&sXh[ r0   *LDN + c0+8];
        ah[kt][3] = *(u32*)&sXh[(r0+8)*LDN + c0+8];
        al[kt][0] = *(u32*)&sXl[ r0   *LDN + c0];
        al[kt][1] = *(u32*)&sXl[(r0+8)*LDN + c0];
        al[kt][2] = *(u32*)&sXl[ r0   *LDN + c0+8];
        al[kt][3] = *(u32*)&sXl[(r0+8)*LDN + c0+8];
    }
    float Z0 = 0.0f, Z1 = 0.0f;

    for (int it = 0; it < 32; ++it) {
        if (it+1 < 32) {
            stage_nat(smb+O_E+((it+1)&1)*EBUF, smb+O_E+((it+1)&1)*EBUF+NATB,
                      g_eHi + (size_t)(b*4096+(it+1)*128)*64,
                      g_eLo + (size_t)(b*4096+(it+1)*128)*64, tid);
            CPA_COMMIT();
            CPA_WAIT1();
        } else {
            CPA_WAIT0();
        }
        __syncthreads();
        u32 eb = smb + O_E + (it&1)*EBUF + lbaseN;
        #pragma unroll
        for (int half = 0; half < 2; half++) {
            float c[8][4];
            #pragma unroll
            for (int n = 0; n < 8; n++)
                c[n][0]=c[n][1]=c[n][2]=c[n][3]=0.0f;
            #pragma unroll
            for (int kt = 0; kt < 4; kt++) {
                u32 BH[16], BL[16];
                #pragma unroll
                for (int nbp = 0; nbp < 4; nbp++) {
                    u32 aH = eb + (u32)(((half*64 + nbp*16)*LDN + kt*16)*2);
                    ldm4(BH + nbp*4, aH);
                    ldm4(BL + nbp*4, aH + NATB);
                }
                #pragma unroll
                for (int n = 0; n < 8; n++) {
                    u32 ix = (n>>1)*4 + (n&1)*2;
                    mma_bf16(c[n], ah[kt][0],ah[kt][1],ah[kt][2],ah[kt][3], BH[ix],BH[ix+1]);
                    mma_bf16(c[n], ah[kt][0],ah[kt][1],ah[kt][2],ah[kt][3], BL[ix],BL[ix+1]);
                    mma_bf16(c[n], al[kt][0],al[kt][1],al[kt][2],al[kt][3], BH[ix],BH[ix+1]);
                }
            }
            #pragma unroll
            for (int n = 0; n < 8; n++) {
                Z0 += ex2f_(c[n][0]*L2E) + ex2f_(c[n][1]*L2E);
                Z1 += ex2f_(c[n][2]*L2E) + ex2f_(c[n][3]*L2E);
            }
        }
        __syncthreads();
    }
    Z0 += __shfl_xor_sync(0xffffffffu, Z0, 1);
    Z0 += __shfl_xor_sync(0xffffffffu, Z0, 2);
    Z1 += __shfl_xor_sync(0xffffffffu, Z1, 1);
    Z1 += __shfl_xor_sync(0xffffffffu, Z1, 2);
    if (t == 0) {
        g_rz[b*4096 + j0 + w*16 + g    ] = 1.0f/Z0;
        g_rz[b*4096 + j0 + w*16 + g + 8] = 1.0f/Z1;
    }
}

// ---------------------------------------------------------------------------
// Kernel 3: out[i,d] = sum_j ex2(s_ji*L2E)*rz_j * x[j,d].
// MMA2 B now comes from the SAME natural x tile via ldmatrix.trans — the xT
// copy (global arrays, staging, smem buffers) is gone.
// ---------------------------------------------------------------------------
__global__ void __launch_bounds__(256) out_kernel(float* __restrict__ out)
{
    extern __shared__ char smc[];
    u32 smb = smem_u32(smc);
    const int O_E = 0, O_X = 36864, O_RZ = 110592;
    const int NATB = 18432, XBUF = 36864;
    int tid = threadIdx.x, w = tid>>5, lane = tid&31;
    int g = lane>>2, t = lane&3;
    int b = blockIdx.x >> 5, i0 = (blockIdx.x & 31)*128;
    // non-trans (MMA1 B: rows = n = j)
    int row_l  = ((lane>>4)<<3) | (lane&7);
    int koff_l = ((lane>>3)&1)<<3;
    u32 lbaseN = (u32)(row_l*LDN + koff_l)*2;
    // trans (MMA2 B: rows = k = j, cols = n = d)
    int rowT = (((lane>>3)&1)<<3) | (lane&7);
    int colT = (lane>>4)<<3;
    u32 lbaseT = (u32)(rowT*LDN + colT)*2;

    stage_nat(smb+O_E, smb+O_E+NATB,
              g_eHi + (size_t)(b*4096+i0)*64,
              g_eLo + (size_t)(b*4096+i0)*64, tid);
    CPA_COMMIT();
    stage_nat(smb+O_X, smb+O_X+NATB,
              g_xHi + (size_t)(b*4096)*64,
              g_xLo + (size_t)(b*4096)*64, tid);
    if (tid < 32) cpa16(smb+O_RZ + tid*16, g_rz + b*4096 + tid*4);
    CPA_COMMIT();
    CPA_WAIT1();
    __syncthreads();

    const __nv_bfloat16* sEh = (const __nv_bfloat16*)(smc + O_E);
    const __nv_bfloat16* sEl = (const __nv_bfloat16*)(smc + O_E + NATB);
    u32 eh[4][4], el[4][4];
    int r0 = w*16 + g;
    #pragma unroll
    for (int kt = 0; kt < 4; kt++) {
        int c0 = kt*16 + t*2;
        eh[kt][0] = *(u32*)&sEh[ r0   *LDN + c0];
        eh[kt][1] = *(u32*)&sEh[(r0+8)*LDN + c0];
        eh[kt][2] = *(u32*)&sEh[ r0   *LDN + c0+8];
        eh[kt][3] = *(u32*)&sEh[(r0+8)*LDN + c0+8];
        el[kt][0] = *(u32*)&sEl[ r0   *LDN + c0];
        el[kt][1] = *(u32*)&sEl[(r0+8)*LDN + c0];
        el[kt][2] = *(u32*)&sEl[ r0   *LDN + c0+8];
        el[kt][3] = *(u32*)&sEl[(r0+8)*LDN + c0+8];
    }
    float acc[8][4];
    #pragma unroll
    for (int n = 0; n < 8; n++)
        acc[n][0]=acc[n][1]=acc[n][2]=acc[n][3]=0.0f;

    for (int jt = 0; jt < 32; ++jt) {
        if (jt+1 < 32) {
            int nb = (jt+1) & 1;
            stage_nat(smb+O_X+nb*XBUF, smb+O_X+nb*XBUF+NATB,
                      g_xHi + (size_t)(b*4096+(jt+1)*128)*64,
                      g_xLo + (size_t)(b*4096+(jt+1)*128)*64, tid);
            if (tid < 32) cpa16(smb+O_RZ+nb*512 + tid*16,
                                g_rz + b*4096 + (jt+1)*128 + tid*4);
            CPA_COMMIT();
            CPA_WAIT1();
        } else {
            CPA_WAIT0();
        }
        __syncthreads();
        int cb = jt & 1;
        u32 xbN = smb + O_X + cb*XBUF + lbaseN;
        u32 xbT = smb + O_X + cb*XBUF + lbaseT;
        const float* sRZ = (const float*)(smc + O_RZ + cb*512);

        #pragma unroll
        for (int half = 0; half < 2; half++) {
            // MMA1: S^T[i][j-half 64]
            float c[8][4];
            #pragma unroll
            for (int n = 0; n < 8; n++)
                c[n][0]=c[n][1]=c[n][2]=c[n][3]=0.0f;
            #pragma unroll
            for (int kt = 0; kt < 4; kt++) {
                u32 BH[16], BL[16];
                #pragma unroll
                for (int nbp = 0; nbp < 4; nbp++) {
                    u32 aH = xbN + (u32)(((half*64 + nbp*16)*LDN + kt*16)*2);
                    ldm4(BH + nbp*4, aH);
                    ldm4(BL + nbp*4, aH + NATB);
                }
                #pragma unroll
                for (int n = 0; n < 8; n++) {
                    u32 ix = (n>>1)*4 + (n&1)*2;
                    mma_bf16(c[n], eh[kt][0],eh[kt][1],eh[kt][2],eh[kt][3], BH[ix],BH[ix+1]);
                    mma_bf16(c[n], eh[kt][0],eh[kt][1],eh[kt][2],eh[kt][3], BL[ix],BL[ix+1]);
                    mma_bf16(c[n], el[kt][0],el[kt][1],el[kt][2],el[kt][3], BH[ix],BH[ix+1]);
                }
            }
            // epilogue: p = ex2(s*L2E)*rz_j -> bf16 hi/lo A2 fragments (regs)
            u32 H0[8], H1[8], L0[8], L1[8];
            #pragma unroll
            for (int n = 0; n < 8; n++) {
                float rza = sRZ[half*64 + n*8 + t*2];
                float rzb = sRZ[half*64 + n*8 + t*2 + 1];
                float p0 = ex2f_(c[n][0]*L2E)*rza;
                float p1 = ex2f_(c[n][1]*L2E)*rzb;
                float p2 = ex2f_(c[n][2]*L2E)*rza;
                float p3 = ex2f_(c[n][3]*L2E)*rzb;
                __nv_bfloat162 h01 = __floats2bfloat162_rn(p0, p1);
                __nv_bfloat162 l01 = __floats2bfloat162_rn(p0 - __bfloat162float(h01.x),
                                                           p1 - __bfloat162float(h01.y));
                __nv_bfloat162 h23 = __floats2bfloat162_rn(p2, p3);
                __nv_bfloat162 l23 = __floats2bfloat162_rn(p2 - __bfloat162float(h23.x),
                                                           p3 - __bfloat162float(h23.y));
                H0[n] = bits2(h01); L0[n] = bits2(l01);
                H1[n] = bits2(h23); L1[n] = bits2(l23);
            }
            // MMA2: acc[i][d] += P^T(half) * x(half) via trans-ldmatrix
            #pragma unroll
            for (int kt2 = 0; kt2 < 4; kt2++) {
                u32 a0 = H0[2*kt2], a2 = H0[2*kt2+1];
                u32 a1 = H1[2*kt2], a3 = H1[2*kt2+1];
                u32 q0 = L0[2*kt2], q2 = L0[2*kt2+1];
                u32 q1 = L1[2*kt2], q3 = L1[2*kt2+1];
                u32 TH[16], TL[16];
                #pragma unroll
                for (int nbp = 0; nbp < 4; nbp++) {
                    u32 aT = xbT + (u32)(((half*64 + kt2*16)*LDN + nbp*16)*2);
                    ldm4t(TH + nbp*4, aT);
                    ldm4t(TL + nbp*4, aT + NATB);
                }
                #pragma unroll
                for (int n = 0; n < 8; n++) {
                    u32 ix = (n>>1)*4 + (n&1)*2;
                    mma_bf16(acc[n], a0,a1,a2,a3, TH[ix],TH[ix+1]);
                    mma_bf16(acc[n], a0,a1,a2,a3, TL[ix],TL[ix+1]);
                    mma_bf16(acc[n], q0,q1,q2,q3, TH[ix],TH[ix+1]);
                }
            }
        }
        __syncthreads();
    }
    // store: acc[n][0..1] -> (i=16w+g, d=n*8+t*2), acc[n][2..3] -> row +8
    int i = i0 + 16*w + g;
    #pragma unroll
    for (int n = 0; n < 8; n++) {
        int d = n*8 + t*2;
        *(float2*)&out[((size_t)(b*4096 + i    ))*64 + d] = make_float2(acc[n][0], acc[n][1]);
        *(float2*)&out[((size_t)(b*4096 + i + 8))*64 + d] = make_float2(acc[n][2], acc[n][3]);
    }
}

// ---------------------------------------------------------------------------
extern "C" void kernel_launch(void* const* d_in, const int* in_sizes, int n_in,
                              void* d_out, int out_size)
{
    (void)in_sizes; (void)n_in; (void)out_size;
    const float* x  = (const float*)d_in[0];
    const float* W1 = (const float*)d_in[1];
    const float* b1 = (const float*)d_in[2];
    const float* W2 = (const float*)d_in[3];
    const float* b2 = (const float*)d_in[4];
    float* out = (float*)d_out;

    const int SMEM_STATS = 110592;   // x(h+l) + 2 x enc(h+l) buffers
    const int SMEM_OUT   = 111616;   // enc(h+l) + 2x x-buf(h+l) + 2x rz
    cudaFuncSetAttribute(stats_kernel, cudaFuncAttributeMaxDynamicSharedMemorySize, SMEM_STATS);
    cudaFuncSetAttribute(out_kernel,   cudaFuncAttributeMaxDynamicSharedMemorySize, SMEM_OUT);

    mlp_kernel<<<512, 256>>>(x, W1, b1, W2, b2);
    stats_kernel<<<128, 256, SMEM_STATS>>>();
    out_kernel<<<128, 256, SMEM_OUT>>>(out);
}